// round 2
// baseline (speedup 1.0000x reference)
#include <cuda_runtime.h>
#include <cuda_bf16.h>

// Problem: GCNConv (1 feature) + sigmoid. N<=1,048,576 nodes, E<=32M edges.
// out[d] = sigmoid( dinv[d] * ( sum_{e: dst=d} dinv[src]*x[src]*W  +  dinv[d]*x[d]*W ) + b )
// where dinv = rsqrt(deg), deg includes self-loop.

#define MAXN        1048576
#define BIN_SHIFT   14
#define BIN_NODES   16384          // nodes per bin (smem accumulator size)
#define NBINS_MAX   64
#define NSEG        8              // cursor decentralization per bin
#define SEG_CAP     72000          // expected ~65.5K edges per (bin,seg); >25 sd margin
#define BPB         6              // accumulate blocks per bin
#define TILE        2048           // binning tile (edges per block iteration)

// ---- scratch (__device__ globals: allocation-free rule) ----
__device__ int            g_ideg[MAXN];
__device__ float          g_dinv[MAXN];
__device__ float          g_y[MAXN];
__device__ float          g_S[MAXN];
__device__ int            g_cur[NBINS_MAX * NSEG];
__device__ int            g_bsrc[NBINS_MAX * NSEG * SEG_CAP];       // 147 MB
__device__ unsigned short g_bd16[NBINS_MAX * NSEG * SEG_CAP];       //  74 MB

// ---------------------------------------------------------------------------
__global__ void k_init(int n) {
    int i = blockIdx.x * blockDim.x + threadIdx.x;
    if (i < n) { g_ideg[i] = 0; g_S[i] = 0.0f; }
    if (i < NBINS_MAX * NSEG) g_cur[i] = 0;
}

// ---------------------------------------------------------------------------
// Binning pass: partition edges by dst>>14 with smem-staged multisplit so the
// binned writes are coalesced runs. Each block uses cursor segment blockIdx&7.
__global__ void k_bin(const int* __restrict__ src,
                      const int* __restrict__ dst, int e) {
    __shared__ int            s_cnt[NBINS_MAX];
    __shared__ int            s_base[NBINS_MAX];
    __shared__ int            s_gbase[NBINS_MAX];
    __shared__ int            s_src[TILE];
    __shared__ unsigned short s_d16[TILE];
    __shared__ unsigned char  s_bin[TILE];

    const int tid = threadIdx.x;
    const int seg = blockIdx.x & (NSEG - 1);
    const int ntiles = (e + TILE - 1) / TILE;

    for (int tile = blockIdx.x; tile < ntiles; tile += gridDim.x) {
        const int tbase = tile * TILE;
        const int tcnt  = min(TILE, e - tbase);

        if (tid < NBINS_MAX) s_cnt[tid] = 0;
        __syncthreads();

        int rs[8], rofs[8];
        unsigned short r16[8];
        unsigned char  rb[8];
#pragma unroll
        for (int k = 0; k < 8; k++) {
            int idx = tbase + k * 256 + tid;
            if (idx < e) {
                int s = src[idx];
                int d = dst[idx];
                rs[k]  = s;
                r16[k] = (unsigned short)(d & (BIN_NODES - 1));
                rb[k]  = (unsigned char)(d >> BIN_SHIFT);
                rofs[k] = atomicAdd(&s_cnt[rb[k]], 1);
            } else {
                rofs[k] = -1;
            }
        }
        __syncthreads();

        if (tid == 0) {                       // serial 64-entry prefix (cheap)
            int run = 0;
#pragma unroll
            for (int b = 0; b < NBINS_MAX; b++) { s_base[b] = run; run += s_cnt[b]; }
        }
        __syncthreads();

        if (tid < NBINS_MAX)                  // reserve global ranges (512 cursor addrs)
            s_gbase[tid] = atomicAdd(&g_cur[tid * NSEG + seg], s_cnt[tid]);

#pragma unroll
        for (int k = 0; k < 8; k++) {
            if (rofs[k] >= 0) {
                int p = s_base[rb[k]] + rofs[k];
                s_src[p] = rs[k];
                s_d16[p] = r16[k];
                s_bin[p] = rb[k];
            }
        }
        __syncthreads();

        // flush: per-bin contiguous runs -> coalesced global writes
        for (int i = tid; i < tcnt; i += blockDim.x) {
            int b   = s_bin[i];
            int idx = s_gbase[b] + (i - s_base[b]);
            if (idx < SEG_CAP) {
                int off = (b * NSEG + seg) * SEG_CAP + idx;
                g_bsrc[off] = s_src[i];
                g_bd16[off] = s_d16[i];
            }
        }
        __syncthreads();  // before s_cnt reuse
    }
}

// ---------------------------------------------------------------------------
// Degree accumulation: per-bin smem int counters, only dst16 stream needed.
__global__ void k_degbin(int n) {
    extern __shared__ int acc[];              // BIN_NODES ints (64KB)
    const int tid = threadIdx.x;
    const int bin = blockIdx.x / BPB;
    const int q   = blockIdx.x % BPB;

    for (int i = tid; i < BIN_NODES; i += blockDim.x) acc[i] = 0;
    __syncthreads();

    for (int seg = 0; seg < NSEG; seg++) {
        int cnt = min(g_cur[bin * NSEG + seg], SEG_CAP);
        int lo  = (int)((long long)cnt * q / BPB);
        int hi  = (int)((long long)cnt * (q + 1) / BPB);
        const unsigned short* p = &g_bd16[(bin * NSEG + seg) * SEG_CAP];
        for (int i = lo + tid; i < hi; i += blockDim.x)
            atomicAdd(&acc[p[i]], 1);
    }
    __syncthreads();

    const int nb = bin << BIN_SHIFT;
    for (int i = tid; i < BIN_NODES; i += blockDim.x) {
        int node = nb + i;
        if (node < n && acc[i]) atomicAdd(&g_ideg[node], acc[i]);
    }
}

// ---------------------------------------------------------------------------
// Per-node: dinv = rsqrt(deg+1)   (+1 = self-loop), y = x*W*dinv
__global__ void k_node(const float* __restrict__ x,
                       const float* __restrict__ W, int n) {
    int i = blockIdx.x * blockDim.x + threadIdx.x;
    if (i < n) {
        float w = __ldg(W);
        float dinv = rsqrtf((float)(g_ideg[i] + 1));
        g_dinv[i] = dinv;
        g_y[i]    = x[i] * w * dinv;
    }
}

// ---------------------------------------------------------------------------
// Scatter accumulation: gather y[src] (random L2), accumulate into smem float
// accumulator for this bin's 16384 dst nodes, flush once with global REDs.
__global__ void k_scatbin(int n) {
    extern __shared__ float facc[];           // BIN_NODES floats (64KB)
    const int tid = threadIdx.x;
    const int bin = blockIdx.x / BPB;
    const int q   = blockIdx.x % BPB;

    for (int i = tid; i < BIN_NODES; i += blockDim.x) facc[i] = 0.0f;
    __syncthreads();

    for (int seg = 0; seg < NSEG; seg++) {
        int cnt = min(g_cur[bin * NSEG + seg], SEG_CAP);
        int lo  = (int)((long long)cnt * q / BPB);
        int hi  = (int)((long long)cnt * (q + 1) / BPB);
        const int off = (bin * NSEG + seg) * SEG_CAP;
        const int* __restrict__ ps            = &g_bsrc[off];
        const unsigned short* __restrict__ pd = &g_bd16[off];
        for (int i = lo + tid; i < hi; i += blockDim.x) {
            float v = __ldg(&g_y[ps[i]]);
            atomicAdd(&facc[pd[i]], v);
        }
    }
    __syncthreads();

    const int nb = bin << BIN_SHIFT;
    for (int i = tid; i < BIN_NODES; i += blockDim.x) {
        int node = nb + i;
        if (node < n && facc[i] != 0.0f) atomicAdd(&g_S[node], facc[i]);
    }
}

// ---------------------------------------------------------------------------
__global__ void k_final(float* __restrict__ out,
                        const float* __restrict__ b, int n) {
    int i = blockIdx.x * blockDim.x + threadIdx.x;
    if (i < n) {
        float z = g_dinv[i] * (g_S[i] + g_y[i]) + __ldg(b);
        out[i] = 1.0f / (1.0f + __expf(-z));
    }
}

// ---------------------------------------------------------------------------
extern "C" void kernel_launch(void* const* d_in, const int* in_sizes, int n_in,
                              void* d_out, int out_size) {
    const float* x    = (const float*)d_in[0];
    const int*   eidx = (const int*)  d_in[1];
    const float* W    = (const float*)d_in[2];
    const float* b    = (const float*)d_in[3];
    float* out = (float*)d_out;

    int n = in_sizes[0];
    int e = in_sizes[1] / 2;
    const int* src = eidx;
    const int* dst = eidx + e;

    const int TPB = 256;
    int gn = (n + TPB - 1) / TPB;
    int nbins = (n + BIN_NODES - 1) >> BIN_SHIFT;

    static int attr_done = 0;  // idempotent attribute set (not a work guard)
    cudaFuncSetAttribute(k_degbin,  cudaFuncAttributeMaxDynamicSharedMemorySize, BIN_NODES * 4);
    cudaFuncSetAttribute(k_scatbin, cudaFuncAttributeMaxDynamicSharedMemorySize, BIN_NODES * 4);
    (void)attr_done;

    k_init   <<<gn, TPB>>>(n);
    k_bin    <<<1024, 256>>>(src, dst, e);
    k_degbin <<<nbins * BPB, 256, BIN_NODES * 4>>>(n);
    k_node   <<<gn, TPB>>>(x, W, n);
    k_scatbin<<<nbins * BPB, 256, BIN_NODES * 4>>>(n);
    k_final  <<<gn, TPB>>>(out, b, n);
}

// round 4
// speedup vs baseline: 1.6937x; 1.6937x over previous
#include <cuda_runtime.h>
#include <cuda_bf16.h>

// GCNConv (1 in/out feature, self-loops, symmetric norm) + sigmoid.
// out[d] = sigmoid( dinv[d]*( SUM_{e:dst=d} dinv[src]*x[src]*W + dinv[d]*x[d]*W ) + b )
// Roofline: ~96M random L2 sector-ops @ ~172-184 ops/cyc  =>  ~330-360us floor.

#define MAXN 1048576

__device__ int   g_ideg[MAXN];   // in-degree (self-loop added as +1 later)
__device__ float g_dinv[MAXN];   // rsqrt(deg)
__device__ float g_y[MAXN];      // x * W * dinv
__device__ float g_S[MAXN];      // sum of incoming y[src]

// ---------------------------------------------------------------------------
__global__ void k_init(int n4) {
    int i = blockIdx.x * blockDim.x + threadIdx.x;
    if (i < n4) {
        reinterpret_cast<int4*>(g_ideg)[i]  = make_int4(0, 0, 0, 0);
        reinterpret_cast<float4*>(g_S)[i]   = make_float4(0.f, 0.f, 0.f, 0.f);
    }
}

// ---------------------------------------------------------------------------
// Degree: 8 edges per thread (2x int4 coalesced reads), 8 REDs.
__global__ void k_degree(const int* __restrict__ dst, int e8, int e) {
    int i = blockIdx.x * blockDim.x + threadIdx.x;
    if (i < e8) {
        const int4* p = reinterpret_cast<const int4*>(dst) + i * 2;
        int4 a = p[0];
        int4 b = p[1];
        atomicAdd(&g_ideg[a.x], 1);
        atomicAdd(&g_ideg[a.y], 1);
        atomicAdd(&g_ideg[a.z], 1);
        atomicAdd(&g_ideg[a.w], 1);
        atomicAdd(&g_ideg[b.x], 1);
        atomicAdd(&g_ideg[b.y], 1);
        atomicAdd(&g_ideg[b.z], 1);
        atomicAdd(&g_ideg[b.w], 1);
    }
    int t = e8 * 8 + i;
    if (i < (e - e8 * 8)) {
        atomicAdd(&g_ideg[dst[t]], 1);
    }
}

// ---------------------------------------------------------------------------
// Per-node: dinv = rsqrt(deg+1)  (+1 self-loop), y = x*W*dinv.  float4.
__global__ void k_node(const float* __restrict__ x,
                       const float* __restrict__ W, int n4) {
    int i = blockIdx.x * blockDim.x + threadIdx.x;
    if (i < n4) {
        float w  = __ldg(W);
        int4  dg = reinterpret_cast<const int4*>(g_ideg)[i];
        float4 xv = reinterpret_cast<const float4*>(x)[i];
        float4 dv, yv;
        dv.x = rsqrtf((float)(dg.x + 1));
        dv.y = rsqrtf((float)(dg.y + 1));
        dv.z = rsqrtf((float)(dg.z + 1));
        dv.w = rsqrtf((float)(dg.w + 1));
        yv.x = xv.x * w * dv.x;
        yv.y = xv.y * w * dv.y;
        yv.z = xv.z * w * dv.z;
        yv.w = xv.w * w * dv.w;
        reinterpret_cast<float4*>(g_dinv)[i] = dv;
        reinterpret_cast<float4*>(g_y)[i]    = yv;
    }
}

// ---------------------------------------------------------------------------
// Scatter: 8 edges/thread. Gathers issued first (MLP=8), then 8 REDs.
__global__ void k_scatter(const int* __restrict__ src,
                          const int* __restrict__ dst, int e8, int e) {
    int i = blockIdx.x * blockDim.x + threadIdx.x;
    if (i < e8) {
        const int4* ps = reinterpret_cast<const int4*>(src) + i * 2;
        const int4* pd = reinterpret_cast<const int4*>(dst) + i * 2;
        int4 s0 = ps[0];
        int4 s1 = ps[1];
        int4 d0 = pd[0];
        int4 d1 = pd[1];
        float v0 = __ldg(&g_y[s0.x]);
        float v1 = __ldg(&g_y[s0.y]);
        float v2 = __ldg(&g_y[s0.z]);
        float v3 = __ldg(&g_y[s0.w]);
        float v4 = __ldg(&g_y[s1.x]);
        float v5 = __ldg(&g_y[s1.y]);
        float v6 = __ldg(&g_y[s1.z]);
        float v7 = __ldg(&g_y[s1.w]);
        atomicAdd(&g_S[d0.x], v0);
        atomicAdd(&g_S[d0.y], v1);
        atomicAdd(&g_S[d0.z], v2);
        atomicAdd(&g_S[d0.w], v3);
        atomicAdd(&g_S[d1.x], v4);
        atomicAdd(&g_S[d1.y], v5);
        atomicAdd(&g_S[d1.z], v6);
        atomicAdd(&g_S[d1.w], v7);
    }
    int t = e8 * 8 + i;
    if (i < (e - e8 * 8)) {
        atomicAdd(&g_S[dst[t]], __ldg(&g_y[src[t]]));
    }
}

// ---------------------------------------------------------------------------
// Finalize: out = sigmoid(dinv*(S + y) + b).  float4.
__global__ void k_final(float* __restrict__ out,
                        const float* __restrict__ b, int n4) {
    int i = blockIdx.x * blockDim.x + threadIdx.x;
    if (i < n4) {
        float bb = __ldg(b);
        float4 dv = reinterpret_cast<const float4*>(g_dinv)[i];
        float4 sv = reinterpret_cast<const float4*>(g_S)[i];
        float4 yv = reinterpret_cast<const float4*>(g_y)[i];
        float4 o;
        float z0 = dv.x * (sv.x + yv.x) + bb;
        float z1 = dv.y * (sv.y + yv.y) + bb;
        float z2 = dv.z * (sv.z + yv.z) + bb;
        float z3 = dv.w * (sv.w + yv.w) + bb;
        o.x = 1.0f / (1.0f + __expf(-z0));
        o.y = 1.0f / (1.0f + __expf(-z1));
        o.z = 1.0f / (1.0f + __expf(-z2));
        o.w = 1.0f / (1.0f + __expf(-z3));
        reinterpret_cast<float4*>(out)[i] = o;
    }
}

// Tail for n % 4 != 0 (not hit for N=1M, kept for generality)
__global__ void k_final_tail(float* __restrict__ out,
                             const float* __restrict__ b, int n4, int n) {
    int i = n4 * 4 + blockIdx.x * blockDim.x + threadIdx.x;
    if (i < n) {
        float z = g_dinv[i] * (g_S[i] + g_y[i]) + __ldg(b);
        out[i] = 1.0f / (1.0f + __expf(-z));
    }
}
__global__ void k_node_tail(const float* __restrict__ x,
                            const float* __restrict__ W, int n4, int n) {
    int i = n4 * 4 + blockIdx.x * blockDim.x + threadIdx.x;
    if (i < n) {
        float w = __ldg(W);
        float dinv = rsqrtf((float)(g_ideg[i] + 1));
        g_dinv[i] = dinv;
        g_y[i] = x[i] * w * dinv;
    }
}
__global__ void k_init_tail(int n4, int n) {
    int i = n4 * 4 + blockIdx.x * blockDim.x + threadIdx.x;
    if (i < n) { g_ideg[i] = 0; g_S[i] = 0.0f; }
}

// ---------------------------------------------------------------------------
extern "C" void kernel_launch(void* const* d_in, const int* in_sizes, int n_in,
                              void* d_out, int out_size) {
    const float* x    = (const float*)d_in[0];
    const int*   eidx = (const int*)  d_in[1];
    const float* W    = (const float*)d_in[2];
    const float* b    = (const float*)d_in[3];
    float* out = (float*)d_out;

    int n = in_sizes[0];
    int e = in_sizes[1] / 2;
    const int* src = eidx;
    const int* dst = eidx + e;

    int n4 = n / 4;
    int e8 = e / 8;

    const int TPB = 256;
    int gn4 = (n4 + TPB - 1) / TPB;
    int ge8 = (e8 + TPB - 1) / TPB;

    k_init   <<<gn4, TPB>>>(n4);
    if (n % 4) k_init_tail<<<1, 256>>>(n4, n);
    k_degree <<<ge8, TPB>>>(dst, e8, e);
    k_node   <<<gn4, TPB>>>(x, W, n4);
    if (n % 4) k_node_tail<<<1, 256>>>(x, W, n4, n);
    k_scatter<<<ge8, TPB>>>(src, dst, e8, e);
    k_final  <<<gn4, TPB>>>(out, b, n4);
    if (n % 4) k_final_tail<<<1, 256>>>(out, b, n4, n);
}